// round 11
// baseline (speedup 1.0000x reference)
#include <cuda_runtime.h>
#include <cstdint>

// EmbeddingBag mode='sum'.
//   out[b][:] = sum_{i in [offsets[b], offsets[b+1])} W[indices[i]][:]
//
// Warp per bag. Lane-group g = lane>>3 owns index i+g; each lane loads 8
// dims (32B) with one 256-bit load -> one warp-load = 4 rows (1024B).
// L2 policy: rows < pin_rows (88MB, ~70% of L2) use L2::evict_last and stay
// resident across graph replays; all other rows use the DEFAULT policy so
// their intra-launch reuse is kept (evict_first in R5/R7 destroyed it) while
// still evicting before the pinned lines.
// End of bag: shfl.xor (8,16) folds the 4 groups; lanes 0-7 store 2x float4.

#define EMB_DIM 64

__device__ __forceinline__ void ld8_last(const float* p, float* v) {
    uint32_t r0,r1,r2,r3,r4,r5,r6,r7;
    asm("ld.global.nc.L2::evict_last.v8.b32 {%0,%1,%2,%3,%4,%5,%6,%7}, [%8];"
        : "=r"(r0),"=r"(r1),"=r"(r2),"=r"(r3),
          "=r"(r4),"=r"(r5),"=r"(r6),"=r"(r7) : "l"(p));
    v[0]=__uint_as_float(r0); v[1]=__uint_as_float(r1);
    v[2]=__uint_as_float(r2); v[3]=__uint_as_float(r3);
    v[4]=__uint_as_float(r4); v[5]=__uint_as_float(r5);
    v[6]=__uint_as_float(r6); v[7]=__uint_as_float(r7);
}
__device__ __forceinline__ void ld8_default(const float* p, float* v) {
    uint32_t r0,r1,r2,r3,r4,r5,r6,r7;
    asm("ld.global.nc.v8.b32 {%0,%1,%2,%3,%4,%5,%6,%7}, [%8];"
        : "=r"(r0),"=r"(r1),"=r"(r2),"=r"(r3),
          "=r"(r4),"=r"(r5),"=r"(r6),"=r"(r7) : "l"(p));
    v[0]=__uint_as_float(r0); v[1]=__uint_as_float(r1);
    v[2]=__uint_as_float(r2); v[3]=__uint_as_float(r3);
    v[4]=__uint_as_float(r4); v[5]=__uint_as_float(r5);
    v[6]=__uint_as_float(r6); v[7]=__uint_as_float(r7);
}
__device__ __forceinline__ void ld_row8(const float* __restrict__ W,
                                        int r, int sublane, int pin_rows,
                                        float* v) {
    const float* p = W + (size_t)r * EMB_DIM + sublane * 8;
    if (r < pin_rows) ld8_last(p, v);     // warp-uniform branch (r broadcast)
    else              ld8_default(p, v);
}

__global__ __launch_bounds__(256, 6) void embag_sum_kernel(
    const float* __restrict__ W,
    const int*   __restrict__ indices,
    const int*   __restrict__ offsets,
    float*       __restrict__ out,
    int n_idx,
    int n_bags,
    int pin_rows)
{
    const int warp    = (blockIdx.x * blockDim.x + threadIdx.x) >> 5;
    const int lane    = threadIdx.x & 31;
    const int grp     = lane >> 3;   // 0..3: which index within a 4-pack
    const int sublane = lane & 7;    // 0..7: which 8-dim slice of the row
    if (warp >= n_bags) return;

    const int start = __ldg(&offsets[warp]);
    const int end   = (warp + 1 < n_bags) ? __ldg(&offsets[warp + 1]) : n_idx;

    float acc0[8], acc1[8];
    #pragma unroll
    for (int k = 0; k < 8; ++k) { acc0[k] = 0.f; acc1[k] = 0.f; }

    int i = start;
    // Main loop: 8 indices per iteration, 2 independent 32B vector loads/lane.
    for (; i + 8 <= end; i += 8) {
        const int ra = __ldg(&indices[i + grp]);
        const int rb = __ldg(&indices[i + 4 + grp]);
        float va[8], vb[8];
        ld_row8(W, ra, sublane, pin_rows, va);
        ld_row8(W, rb, sublane, pin_rows, vb);
        #pragma unroll
        for (int k = 0; k < 8; ++k) { acc0[k] += va[k]; acc1[k] += vb[k]; }
    }
    // 4-wide tail
    if (i + 4 <= end) {
        const int r = __ldg(&indices[i + grp]);
        float v[8];
        ld_row8(W, r, sublane, pin_rows, v);
        #pragma unroll
        for (int k = 0; k < 8; ++k) acc0[k] += v[k];
        i += 4;
    }
    // Final ragged tail (0..3 indices): group-predicated
    {
        const int rem = end - i;
        if (grp < rem) {
            const int r = __ldg(&indices[i + grp]);
            float v[8];
            ld_row8(W, r, sublane, pin_rows, v);
            #pragma unroll
            for (int k = 0; k < 8; ++k) acc1[k] += v[k];
        }
    }

    // Fold the two accumulator sets, then reduce across the 4 lane-groups.
    #pragma unroll
    for (int k = 0; k < 8; ++k) {
        float a = acc0[k] + acc1[k];
        a += __shfl_xor_sync(0xFFFFFFFFu, a, 8);
        a += __shfl_xor_sync(0xFFFFFFFFu, a, 16);
        acc0[k] = a;
    }

    // Lanes 0-7 hold the full sum for dims [lane*8, lane*8+8). Store 2x float4.
    if (lane < 8) {
        float4* o = (float4*)(out + (size_t)warp * EMB_DIM + lane * 8);
        o[0] = make_float4(acc0[0], acc0[1], acc0[2], acc0[3]);
        o[1] = make_float4(acc0[4], acc0[5], acc0[6], acc0[7]);
    }
}

extern "C" void kernel_launch(void* const* d_in, const int* in_sizes, int n_in,
                              void* d_out, int out_size)
{
    const float* W       = (const float*)d_in[0];
    const int*   indices = (const int*)d_in[1];
    const int*   offsets = (const int*)d_in[2];
    float*       out     = (float*)d_out;

    const int n_idx  = in_sizes[1];
    const int n_bags = in_sizes[2];

    const long long table_rows = (long long)in_sizes[0] / EMB_DIM;
    long long pin = (88ll * 1024 * 1024) / (EMB_DIM * sizeof(float));  // rows
    if (pin > table_rows) pin = table_rows;

    const int warps_per_block = 256 / 32;
    const int blocks = (n_bags + warps_per_block - 1) / warps_per_block;

    embag_sum_kernel<<<blocks, 256>>>(W, indices, offsets, out,
                                      n_idx, n_bags, (int)pin);
}

// round 13
// speedup vs baseline: 1.2613x; 1.2613x over previous
#include <cuda_runtime.h>
#include <cstdint>

// EmbeddingBag mode='sum'. No cache hints (R5/R7/R11 showed evict policies
// are neutral-to-harmful here).
//   out[b][:] = sum_{i in [offsets[b], offsets[b+1])} W[indices[i]][:]
//
// Warp per bag. float4 per lane: lane-group grp = lane>>4 (2 groups of 16
// lanes), each group covers one full 256B row per load (16 lanes x 16B).
// Main loop front-batches 4 independent LDG.128 (8 rows, 16 lines in flight
// per warp) while keeping register count low enough for ~80% occupancy —
// the R3/R7/R11 data shows DRAM busy tracks occupancy (independent warp
// streams), so we want R3-level occupancy with R7-level per-warp MLP.
// Reduction: one shfl.xor(16); lanes 0-15 store one float4 each.

#define EMB_DIM 64
#define F4_PER_ROW (EMB_DIM / 4)   // 16 float4 per row -> one per lane-group lane

__global__ __launch_bounds__(256) void embag_sum_kernel(
    const float4* __restrict__ W4,
    const int*    __restrict__ indices,
    const int*    __restrict__ offsets,
    float4*       __restrict__ out4,
    int n_idx,
    int n_bags)
{
    const int warp = (blockIdx.x * blockDim.x + threadIdx.x) >> 5;
    const int lane = threadIdx.x & 31;
    const int grp  = lane >> 4;    // 0..1: which row within a 2-pack
    const int sub  = lane & 15;    // 0..15: which 16B slice of the row
    if (warp >= n_bags) return;

    const int start = __ldg(&offsets[warp]);
    const int end   = (warp + 1 < n_bags) ? __ldg(&offsets[warp + 1]) : n_idx;

    float4 accA = make_float4(0.f, 0.f, 0.f, 0.f);
    float4 accB = make_float4(0.f, 0.f, 0.f, 0.f);

    int i = start;
    // Main loop: 8 indices per iteration via 4 independent 128-bit loads.
    for (; i + 8 <= end; i += 8) {
        const int r0 = __ldg(&indices[i     + grp]);
        const int r1 = __ldg(&indices[i + 2 + grp]);
        const int r2 = __ldg(&indices[i + 4 + grp]);
        const int r3 = __ldg(&indices[i + 6 + grp]);

        const float4 v0 = __ldg(&W4[(size_t)r0 * F4_PER_ROW + sub]);
        const float4 v1 = __ldg(&W4[(size_t)r1 * F4_PER_ROW + sub]);
        const float4 v2 = __ldg(&W4[(size_t)r2 * F4_PER_ROW + sub]);
        const float4 v3 = __ldg(&W4[(size_t)r3 * F4_PER_ROW + sub]);

        accA.x += v0.x; accA.y += v0.y; accA.z += v0.z; accA.w += v0.w;
        accB.x += v1.x; accB.y += v1.y; accB.z += v1.z; accB.w += v1.w;
        accA.x += v2.x; accA.y += v2.y; accA.z += v2.z; accA.w += v2.w;
        accB.x += v3.x; accB.y += v3.y; accB.z += v3.z; accB.w += v3.w;
    }
    // Pair tail: 2 indices at a time (one load per warp).
    for (; i + 2 <= end; i += 2) {
        const int r = __ldg(&indices[i + grp]);
        const float4 v = __ldg(&W4[(size_t)r * F4_PER_ROW + sub]);
        accA.x += v.x; accA.y += v.y; accA.z += v.z; accA.w += v.w;
    }
    // Ragged single index: only group 0 participates.
    if (i < end && grp == 0) {
        const int r = __ldg(&indices[i]);
        const float4 v = __ldg(&W4[(size_t)r * F4_PER_ROW + sub]);
        accB.x += v.x; accB.y += v.y; accB.z += v.z; accB.w += v.w;
    }

    float4 acc;
    acc.x = accA.x + accB.x;
    acc.y = accA.y + accB.y;
    acc.z = accA.z + accB.z;
    acc.w = accA.w + accB.w;

    // Fold the two lane-groups: partner lane is lane^16.
    acc.x += __shfl_xor_sync(0xFFFFFFFFu, acc.x, 16);
    acc.y += __shfl_xor_sync(0xFFFFFFFFu, acc.y, 16);
    acc.z += __shfl_xor_sync(0xFFFFFFFFu, acc.z, 16);
    acc.w += __shfl_xor_sync(0xFFFFFFFFu, acc.w, 16);

    // Lanes 0-15 hold the bag sum for dims [sub*4, sub*4+4).
    if (lane < 16) {
        out4[(size_t)warp * F4_PER_ROW + sub] = acc;
    }
}

extern "C" void kernel_launch(void* const* d_in, const int* in_sizes, int n_in,
                              void* d_out, int out_size)
{
    const float4* W4      = (const float4*)d_in[0];
    const int*    indices = (const int*)d_in[1];
    const int*    offsets = (const int*)d_in[2];
    float4*       out4    = (float4*)d_out;

    const int n_idx  = in_sizes[1];
    const int n_bags = in_sizes[2];

    const int warps_per_block = 256 / 32;
    const int blocks = (n_bags + warps_per_block - 1) / warps_per_block;

    embag_sum_kernel<<<blocks, 256>>>(W4, indices, offsets, out4, n_idx, n_bags);
}